// round 11
// baseline (speedup 1.0000x reference)
#include <cuda_runtime.h>

// LoCon1d: out[b][o][s] = sum_{c,k} in[b][c][s+k-1] * w[o][c][s][k] + bias[o][s]
// B=16, Cin=64, Cout=64, S=1024, K=3 (zero pad)
//
//  1) transpose_kernel: input (B,C,S) -> g_trans[c][1+s][b], zero halo rows
//  2) locon1d_kernel:   S_TILE=8 -> 512 blocks -> 3 resident blocks/SM.
//                       Block-wide cp.async ring (R9 group math, verified).

#define S_LEN   1024
#define CIN     64
#define COUT    64
#define BATCH   16
#define KW      3
#define S_TILE  8
#define O_TILE  16
#define HALO    (S_TILE + 2)        // 10
#define THREADS 256

// transposed input: [c][j=0..1025][b=0..15], j = s+1 (rows 0 and 1025 zero)
#define TR_J    (S_LEN + 2)
__device__ float g_trans[CIN * TR_J * BATCH];

// ring stage: weight 16o*8s*3k floats = 1536B at offset 0,
//             input 10j * (4 f4 + pad handled by 5-stride) = 50 f4 = 800B at 1536
#define W_STAGE_B    1536
#define IN_OFF_B     1536
#define STAGE_BYTES  2560            // 2336 rounded up to 128B multiple
#define N_STAGES     8
#define SMEM_BYTES   (N_STAGES * STAGE_BYTES)   // 20480

typedef unsigned long long u64;

__device__ __forceinline__ u64 splat2(float w) {
    u64 r;
    asm("mov.b64 %0, {%1, %1};" : "=l"(r) : "f"(w));
    return r;
}
__device__ __forceinline__ void fma2(u64 &d, u64 a, u64 b) {
    asm("fma.rn.f32x2 %0, %1, %2, %0;" : "+l"(d) : "l"(a), "l"(b));
}
__device__ __forceinline__ float2 u2f(u64 u) {
    float2 r;
    asm("mov.b64 {%0, %1}, %2;" : "=f"(r.x), "=f"(r.y) : "l"(u));
    return r;
}
__device__ __forceinline__ void cp16(unsigned dst, const void* src) {
    asm volatile("cp.async.cg.shared.global [%0], [%1], 16;" :: "r"(dst), "l"(src));
}
__device__ __forceinline__ void cp_commit() {
    asm volatile("cp.async.commit_group;");
}
__device__ __forceinline__ void cp_wait6() {
    asm volatile("cp.async.wait_group 6;");
}

// ---------------------------------------------------------------------------
// transpose: input[b][c][s] -> g_trans[c][1+s][b]; zero rows j=0 and j=1025
// ---------------------------------------------------------------------------
__global__ void __launch_bounds__(256)
transpose_kernel(const float* __restrict__ input)
{
    __shared__ float tile[BATCH][65];

    const int c  = blockIdx.x;
    const int s0 = blockIdx.y * 64;
    const int tid = threadIdx.x;

    #pragma unroll
    for (int r = 0; r < 4; ++r) {
        const int idx = tid + r * 256;
        const int b  = idx >> 6;
        const int sl = idx & 63;
        tile[b][sl] = input[((size_t)b * CIN + c) * S_LEN + s0 + sl];
    }
    __syncthreads();

    #pragma unroll
    for (int r = 0; r < 4; ++r) {
        const int idx = tid + r * 256;
        const int b  = idx & 15;
        const int sl = idx >> 4;
        g_trans[((size_t)c * TR_J + 1 + s0 + sl) * BATCH + b] = tile[b][sl];
    }

    if (blockIdx.x == 0 && blockIdx.y == 0) {
        for (int e = tid; e < CIN * BATCH; e += 256) {
            const int cc = e >> 4, bb = e & 15;
            g_trans[((size_t)cc * TR_J + 0) * BATCH + bb]        = 0.f;
            g_trans[((size_t)cc * TR_J + TR_J - 1) * BATCH + bb] = 0.f;
        }
    }
}

// ---------------------------------------------------------------------------
// main conv: 512 blocks of 256 threads, 3 blocks/SM resident.
// thread: 1 cout (ow=tid>>4), 2 s (sg=(tid>>2)&3), 4 b (bg=tid&3)
// ---------------------------------------------------------------------------
__global__ void __launch_bounds__(THREADS, 3)
locon1d_kernel(const float* __restrict__ weight,
               const float* __restrict__ bias,
               float* __restrict__ out)
{
    extern __shared__ char smem[];

    const int s0 = blockIdx.x * S_TILE;
    const int o0 = blockIdx.y * O_TILE;
    const int tid = threadIdx.x;
    const unsigned sh_u = (unsigned)__cvta_generic_to_shared(smem);

    // ---- cp.async fill: weight tid<96 (o=tid/6, r6=tid%6), input tid in [96,136)
    const int wo = tid / 6, wr = tid % 6;
    const float* wsrc = weight + ((size_t)(o0 + wo) * CIN) * (S_LEN * 3)
                               + (size_t)s0 * 3 + wr * 4;
    const int inf = tid - 96;                     // 0..39 valid
    const int ij = (inf < 0 ? 0 : inf >> 2);
    const int ib = (inf < 0 ? 0 : inf & 3);
    const float* isrc = g_trans + ((size_t)(s0 + ij)) * BATCH + ib * 4;
    const unsigned wdst_off = (unsigned)(tid * 16);
    const unsigned idst_off = (unsigned)(IN_OFF_B + (5 * ij + ib) * 16);

    auto WISSUE = [&](int c) {
        const unsigned stg = sh_u + (unsigned)((c & (N_STAGES - 1)) * STAGE_BYTES);
        if (tid < 96)
            cp16(stg + wdst_off, wsrc + (size_t)c * (S_LEN * 3));
        else if (tid < 136)
            cp16(stg + idst_off, isrc + (size_t)c * (TR_J * BATCH));
        cp_commit();
    };

    // prologue: 7 stages in flight. Before iter-c wait: commits = 7+c;
    // wait_group 6 -> completed >= c+1 -> group c (stage c) resident.
    WISSUE(0); WISSUE(1); WISSUE(2); WISSUE(3); WISSUE(4); WISSUE(5); WISSUE(6);

    // ---- compute mapping --------------------------------------------------
    const int bg = tid & 3;             // 4 batches (2 f32x2)
    const int sg = (tid >> 2) & 3;      // 2 s each
    const int ow = tid >> 4;            // 0..15, one cout
    const int o     = o0 + ow;
    const int sbase = s0 + 2 * sg;

    const int vofs = 5 * (2 * sg) + bg;          // u2 idx in input part (+5 per d)
    const int wofs = ow * 12 + sg * 3;           // float2 idx in weight part

    u64 acc[2][2];
    acc[0][0] = acc[0][1] = acc[1][0] = acc[1][1] = 0ull;

    for (int c = 0; c < CIN; ++c) {
        cp_wait6();          // stage c resident for MY cp16s
        __syncthreads();     // all threads' cp16s visible; releases slot (c-1)&7

        const char* stg = smem + (c & (N_STAGES - 1)) * STAGE_BYTES;
        const float2* wf2 = reinterpret_cast<const float2*>(stg);
        float2 w01 = wf2[wofs + 0];     // weights (s_loc, k): (0,0) (0,1)
        float2 w23 = wf2[wofs + 1];     //                     (0,2) (1,0)
        float2 w45 = wf2[wofs + 2];     //                     (1,1) (1,2)

        const ulonglong2* vstg =
            reinterpret_cast<const ulonglong2*>(stg + IN_OFF_B);
        ulonglong2 v[4];
        #pragma unroll
        for (int d = 0; d < 4; ++d)
            v[d] = vstg[vofs + 5 * d];

        // ss=0 uses v[0..2] with w01.x, w01.y, w23.x
        // ss=1 uses v[1..3] with w23.y, w45.x, w45.y
        {
            u64 w2;
            w2 = splat2(w01.x); fma2(acc[0][0], v[0].x, w2); fma2(acc[0][1], v[0].y, w2);
            w2 = splat2(w01.y); fma2(acc[0][0], v[1].x, w2); fma2(acc[0][1], v[1].y, w2);
            w2 = splat2(w23.x); fma2(acc[0][0], v[2].x, w2); fma2(acc[0][1], v[2].y, w2);
            w2 = splat2(w23.y); fma2(acc[1][0], v[1].x, w2); fma2(acc[1][1], v[1].y, w2);
            w2 = splat2(w45.x); fma2(acc[1][0], v[2].x, w2); fma2(acc[1][1], v[2].y, w2);
            w2 = splat2(w45.y); fma2(acc[1][0], v[3].x, w2); fma2(acc[1][1], v[3].y, w2);
        }

        // refill stage c+7 -> slot (c-1)&7, released by this iter's barrier.
        if (c + 7 < CIN) WISSUE(c + 7); else cp_commit();
    }

    // ---- epilogue: bias + store ------------------------------------------
    {
        const float2 bz = *reinterpret_cast<const float2*>(bias + (size_t)o * S_LEN + sbase);
        #pragma unroll
        for (int pr = 0; pr < 2; ++pr) {
            const float2 a0 = u2f(acc[0][pr]);   // s=sbase,   batches (b0, b0+1)
            const float2 a1 = u2f(acc[1][pr]);   // s=sbase+1
            const int b0 = bg * 4 + pr * 2;
            float2 r0 = make_float2(a0.x + bz.x, a1.x + bz.y);
            float2 r1 = make_float2(a0.y + bz.x, a1.y + bz.y);
            *reinterpret_cast<float2*>(out + ((size_t)(b0 * COUT + o)) * S_LEN + sbase) = r0;
            *reinterpret_cast<float2*>(out + ((size_t)((b0 + 1) * COUT + o)) * S_LEN + sbase) = r1;
        }
    }
}

extern "C" void kernel_launch(void* const* d_in, const int* in_sizes, int n_in,
                              void* d_out, int out_size) {
    const float* input  = (const float*)d_in[0];
    const float* weight = (const float*)d_in[1];
    const float* bias   = (const float*)d_in[2];
    float* out = (float*)d_out;

    cudaFuncSetAttribute(locon1d_kernel,
                         cudaFuncAttributeMaxDynamicSharedMemorySize, SMEM_BYTES);

    dim3 tgrid(CIN, S_LEN / 64);                 // (64, 16)
    transpose_kernel<<<tgrid, 256>>>(input);

    dim3 grid(S_LEN / S_TILE, COUT / O_TILE);    // (128, 4) = 512 blocks
    locon1d_kernel<<<grid, THREADS, SMEM_BYTES>>>(weight, bias, out);
}

// round 13
// speedup vs baseline: 1.6082x; 1.6082x over previous
#include <cuda_runtime.h>

// LoCon1d: out[b][o][s] = sum_{c,k} in[b][c][s+k-1] * w[o][c][s][k] + bias[o][s]
// B=16, Cin=64, Cout=64, S=1024, K=3 (zero pad)
//
//  1) transpose_kernel: input (B,C,S) -> g_trans[c][1+s][b], zero halo rows
//  2) locon1d_kernel:   thread = 2 couts x 1 s x 16 batches (min instructions
//                       per output); 8-stage block-wide cp.async ring (R9 math).

#define S_LEN   1024
#define CIN     64
#define COUT    64
#define BATCH   16
#define KW      3
#define S_TILE  16
#define O_TILE  16
#define HALO    (S_TILE + 2)        // 18
#define THREADS 128

// transposed input: [c][j=0..1025][b=0..15], j = s+1 (rows 0 and 1025 zero)
#define TR_J    (S_LEN + 2)
__device__ float g_trans[CIN * TR_J * BATCH];

// ring stage: weight [o][s][k] 16*16*3 f32 = 3072B at 0,
//             input 18 rows x 5 f4 (stride-5 pad, 4 used) = 1440B at 3072
#define IN_OFF_B     3072
#define STAGE_BYTES  4608
#define N_STAGES     8
#define SMEM_BYTES   (N_STAGES * STAGE_BYTES)   // 36864

typedef unsigned long long u64;

__device__ __forceinline__ u64 splat2(float w) {
    u64 r;
    asm("mov.b64 %0, {%1, %1};" : "=l"(r) : "f"(w));
    return r;
}
__device__ __forceinline__ void fma2(u64 &d, u64 a, u64 b) {
    asm("fma.rn.f32x2 %0, %1, %2, %0;" : "+l"(d) : "l"(a), "l"(b));
}
__device__ __forceinline__ float2 u2f(u64 u) {
    float2 r;
    asm("mov.b64 {%0, %1}, %2;" : "=f"(r.x), "=f"(r.y) : "l"(u));
    return r;
}
__device__ __forceinline__ void cp16(unsigned dst, const void* src) {
    asm volatile("cp.async.cg.shared.global [%0], [%1], 16;" :: "r"(dst), "l"(src));
}
__device__ __forceinline__ void cp_commit() {
    asm volatile("cp.async.commit_group;");
}
__device__ __forceinline__ void cp_wait6() {
    asm volatile("cp.async.wait_group 6;");
}

// ---------------------------------------------------------------------------
// transpose: input[b][c][s] -> g_trans[c][1+s][b]; zero rows j=0 and j=1025
// ---------------------------------------------------------------------------
__global__ void __launch_bounds__(256)
transpose_kernel(const float* __restrict__ input)
{
    __shared__ float tile[BATCH][65];

    const int c  = blockIdx.x;
    const int s0 = blockIdx.y * 64;
    const int tid = threadIdx.x;

    #pragma unroll
    for (int r = 0; r < 4; ++r) {
        const int idx = tid + r * 256;
        const int b  = idx >> 6;
        const int sl = idx & 63;
        tile[b][sl] = input[((size_t)b * CIN + c) * S_LEN + s0 + sl];
    }
    __syncthreads();

    #pragma unroll
    for (int r = 0; r < 4; ++r) {
        const int idx = tid + r * 256;
        const int b  = idx & 15;
        const int sl = idx >> 4;
        g_trans[((size_t)c * TR_J + 1 + s0 + sl) * BATCH + b] = tile[b][sl];
    }

    if (blockIdx.x == 0 && blockIdx.y == 0) {
        for (int e = tid; e < CIN * BATCH; e += 256) {
            const int cc = e >> 4, bb = e & 15;
            g_trans[((size_t)cc * TR_J + 0) * BATCH + bb]        = 0.f;
            g_trans[((size_t)cc * TR_J + TR_J - 1) * BATCH + bb] = 0.f;
        }
    }
}

// ---------------------------------------------------------------------------
// main conv: 256 blocks x 128 threads.
// thread: og = tid>>4 (couts o0+2og, o0+2og+1), sl = tid&15 (s = s0+sl), 16 b.
// ---------------------------------------------------------------------------
__global__ void __launch_bounds__(THREADS, 3)
locon1d_kernel(const float* __restrict__ weight,
               const float* __restrict__ bias,
               float* __restrict__ out)
{
    extern __shared__ char smem[];

    const int s0 = blockIdx.x * S_TILE;
    const int o0 = blockIdx.y * O_TILE;
    const int tid = threadIdx.x;
    const unsigned sh_u = (unsigned)__cvta_generic_to_shared(smem);

    // ---- cp.async fill per stage ------------------------------------------
    // weight: f4 f in [0,192): o = f/12, r = f%12 -> [o][s][k] layout
    // input:  f2 in [0,72): j = f2/4, bq = f2&3 -> f4 slot 5j+bq (stride-5)
    const int fA = tid, fB = tid + THREADS;
    const float* wsrcA = weight + ((size_t)(o0 + fA / 12) * CIN) * (S_LEN * 3)
                                + (size_t)s0 * 3 + (fA % 12) * 4;
    const float* wsrcB = weight + ((size_t)(o0 + fB / 12) * CIN) * (S_LEN * 3)
                                + (size_t)s0 * 3 + (fB % 12) * 4;
    const int ij = (tid < 72) ? (tid >> 2) : 0;
    const int ib = (tid < 72) ? (tid & 3) : 0;
    const float* isrc = g_trans + ((size_t)(s0 + ij)) * BATCH + ib * 4;
    const unsigned idst_off = (unsigned)(IN_OFF_B + (5 * ij + ib) * 16);

    auto WISSUE = [&](int c) {
        const unsigned stg = sh_u + (unsigned)((c & (N_STAGES - 1)) * STAGE_BYTES);
        cp16(stg + (unsigned)(fA * 16), wsrcA + (size_t)c * (S_LEN * 3));
        if (tid < 64)
            cp16(stg + (unsigned)(fB * 16), wsrcB + (size_t)c * (S_LEN * 3));
        if (tid < 72)
            cp16(stg + idst_off, isrc + (size_t)c * (TR_J * BATCH));
        cp_commit();
    };

    // prologue: 7 stages. Before iter-c wait: commits = 7+c; wait_group 6 ->
    // completed >= c+1 -> group c (stage c) resident. (R9-verified math.)
    WISSUE(0); WISSUE(1); WISSUE(2); WISSUE(3); WISSUE(4); WISSUE(5); WISSUE(6);

    // ---- compute mapping --------------------------------------------------
    const int sl = tid & 15;            // s = s0 + sl
    const int og = tid >> 4;            // 0..7
    const int oA = o0 + 2 * og;
    const int oB = oA + 1;
    const int s  = s0 + sl;

    u64 accA[8], accB[8];
    #pragma unroll
    for (int p = 0; p < 8; ++p) { accA[p] = 0ull; accB[p] = 0ull; }

    for (int c = 0; c < CIN; ++c) {
        cp_wait6();
        __syncthreads();     // stage c visible; slot (c-1)&7 now free

        // refill first: stage c+7 -> slot (c-1)&7 (disjoint from read slot c&7)
        if (c + 7 < CIN) WISSUE(c + 7); else cp_commit();

        const char* stg = smem + (c & (N_STAGES - 1)) * STAGE_BYTES;

        // weights: [o][s][k] floats; bank (16o+3s) mod 32 -> conflict-free
        const float* wf = reinterpret_cast<const float*>(stg);
        float wA[3], wB[3];
        #pragma unroll
        for (int k = 0; k < KW; ++k) {
            wA[k] = wf[(2 * og)     * 48 + sl * 3 + k];
            wB[k] = wf[(2 * og + 1) * 48 + sl * 3 + k];
        }

        // input rows j_l = sl+k, 4 f4 (8 u64) each; 2-phase LDS.128 w/ broadcast
        const ulonglong2* vstg =
            reinterpret_cast<const ulonglong2*>(stg + IN_OFF_B);
        ulonglong2 v[3][4];
        #pragma unroll
        for (int k = 0; k < KW; ++k)
            #pragma unroll
            for (int bq = 0; bq < 4; ++bq)
                v[k][bq] = vstg[5 * (sl + k) + bq];

        #pragma unroll
        for (int k = 0; k < KW; ++k) {
            const u64 a2 = splat2(wA[k]);
            const u64 b2 = splat2(wB[k]);
            #pragma unroll
            for (int bq = 0; bq < 4; ++bq) {
                fma2(accA[2 * bq],     v[k][bq].x, a2);
                fma2(accA[2 * bq + 1], v[k][bq].y, a2);
                fma2(accB[2 * bq],     v[k][bq].x, b2);
                fma2(accB[2 * bq + 1], v[k][bq].y, b2);
            }
        }
    }

    // ---- epilogue: bias + store ------------------------------------------
    {
        const float bzA = bias[(size_t)oA * S_LEN + s];
        const float bzB = bias[(size_t)oB * S_LEN + s];
        #pragma unroll
        for (int p = 0; p < 8; ++p) {
            const float2 a = u2f(accA[p]);
            const float2 b = u2f(accB[p]);
            const int b0 = 2 * p;
            out[((size_t)(b0       * COUT + oA)) * S_LEN + s] = a.x + bzA;
            out[((size_t)((b0 + 1) * COUT + oA)) * S_LEN + s] = a.y + bzA;
            out[((size_t)(b0       * COUT + oB)) * S_LEN + s] = b.x + bzB;
            out[((size_t)((b0 + 1) * COUT + oB)) * S_LEN + s] = b.y + bzB;
        }
    }
}

extern "C" void kernel_launch(void* const* d_in, const int* in_sizes, int n_in,
                              void* d_out, int out_size) {
    const float* input  = (const float*)d_in[0];
    const float* weight = (const float*)d_in[1];
    const float* bias   = (const float*)d_in[2];
    float* out = (float*)d_out;

    cudaFuncSetAttribute(locon1d_kernel,
                         cudaFuncAttributeMaxDynamicSharedMemorySize, SMEM_BYTES);

    dim3 tgrid(CIN, S_LEN / 64);                 // (64, 16)
    transpose_kernel<<<tgrid, 256>>>(input);

    dim3 grid(S_LEN / S_TILE, COUT / O_TILE);    // (64, 4)
    locon1d_kernel<<<grid, THREADS, SMEM_BYTES>>>(weight, bias, out);
}